// round 15
// baseline (speedup 1.0000x reference)
#include <cuda_runtime.h>
#include <cuda_bf16.h>
#include <cstdint>

// ============================================================================
// PNeRF coordinate extension as a chunked affine prefix scan (round 13).
// State (M, t): x_world = x_local @ M + t.  Step: M' = S M ; t' = t + bl*M'[0]
// Round 13 = R12 + DUAL HALF-CHAIN walks: atoms 0-7 and 8-15 walked as two
//   independent chains (2x ILP, half the serial latency), merged by one cmb
//   (k1) / one batch of matvecs (k3). Exact algebra, rounding-level regroup.
// ============================================================================

#define C1    16                 // atoms per chunk (per thread)
#define TPB   192                // chunks per block (6 warps)
#define NW    (TPB/32)
#define Q     (3*C1)             // 48 floats per chunk
#define ROWF  52                 // padded floats per row (208B, conflict-free .128)
#define ROW4  13                 // float4 per row
#define TILE_F (TPB*C1*3)        // 9216 floats per block tile
#define MAXCHUNKS 188160
#define MAXBLK    1024

struct Aff { float m[9]; float t[3]; };

__device__ float g_cs[12 * MAXCHUNKS];          // chunkScan, SoA: [comp][chunk]
__device__ float g_blockComp[MAXBLK * 12];
__device__ float g_basePrefix[MAXBLK * 12];

// ---------------------------------------------------------------------------
// Accurate fp32 sincos (immune to --use_fast_math): Cody-Waite + Cephes polys.
// ---------------------------------------------------------------------------
__device__ __forceinline__ void fsincos(float x, float& s, float& c) {
    float q = rintf(x * 0.6366197723675814f);
    float r = fmaf(q, -1.5707963705062866f, x);
    r = fmaf(q, 4.37113883e-8f, r);
    int iq = (int)q;
    float z = r * r;
    float ps = fmaf(z, -1.9515295891e-4f, 8.3321608736e-3f);
    ps = fmaf(z, ps, -1.6666654611e-1f);
    float sr = fmaf(r * z, ps, r);
    float pc = fmaf(z, 2.443315711809948e-5f, -1.388731625493765e-3f);
    pc = fmaf(z, pc, 4.166664568298827e-2f);
    float cr = fmaf(z * z, pc, fmaf(z, -0.5f, 1.0f));
    bool sw = (iq & 1);
    float ss = sw ? cr : sr;
    float cc = sw ? sr : cr;
    if (iq & 2)        ss = -ss;
    if ((iq + 1) & 2)  cc = -cc;
    s = ss; c = cc;
}

// Theta path: bond_angle in [1.9, 2.1] -> Cody-Waite quadrant is always 1.
__device__ __forceinline__ void fsincos_th(float x, float& s, float& c) {
    float r = (x - 1.5707963705062866f) + 4.37113883e-8f;
    float z = r * r;
    float ps = fmaf(z, -1.9515295891e-4f, 8.3321608736e-3f);
    ps = fmaf(z, ps, -1.6666654611e-1f);
    float sr = fmaf(r * z, ps, r);
    float pc = fmaf(z, 2.443315711809948e-5f, -1.388731625493765e-3f);
    pc = fmaf(z, pc, 4.166664568298827e-2f);
    float cr = fmaf(z * z, pc, fmaf(z, -0.5f, 1.0f));
    s = cr; c = -sr;
}

__device__ __forceinline__ Aff aff_identity() {
    Aff a = {{1,0,0, 0,1,0, 0,0,1}, {0,0,0}};
    return a;
}

// Combine: A earlier (or state), B later composite.
__device__ __forceinline__ Aff cmb(const Aff& A, const Aff& B) {
    Aff r;
#pragma unroll
    for (int i = 0; i < 3; i++) {
        float b0 = B.m[3*i], b1 = B.m[3*i+1], b2 = B.m[3*i+2];
#pragma unroll
        for (int j = 0; j < 3; j++)
            r.m[3*i+j] = fmaf(b0, A.m[j], fmaf(b1, A.m[3+j], b2 * A.m[6+j]));
    }
#pragma unroll
    for (int j = 0; j < 3; j++)
        r.t[j] = fmaf(B.t[0], A.m[j], fmaf(B.t[1], A.m[3+j],
                 fmaf(B.t[2], A.m[6+j], A.t[j])));
    return r;
}

// Givens-factored step: S = Rz(th) * Rx(ph), applied column-wise.
__device__ __forceinline__ void chain_step(float bl, float th, float ph, Aff& s) {
    float st, ct, sp, cp;
    fsincos_th(th, st, ct);
    fsincos(ph, sp, cp);
#pragma unroll
    for (int j = 0; j < 3; j++) {
        float m0 = s.m[j], m1 = s.m[3+j], m2 = s.m[6+j];
        float u  = fmaf(cp, m1, sp * m2);
        float v  = fmaf(cp, m2, -sp * m1);
        float r0 = fmaf(ct, m0, st * u);
        float r1 = fmaf(ct, u, -st * m0);
        s.m[j] = r0; s.m[3+j] = r1; s.m[6+j] = v;
        s.t[j] = fmaf(bl, r0, s.t[j]);
    }
}

// First step from identity: s = S, t = bl*S[0].
__device__ __forceinline__ void first_step(float bl, float th, float ph, Aff& s) {
    float st, ct, sp, cp;
    fsincos_th(th, st, ct);
    fsincos(ph, sp, cp);
    s.m[0] = ct;        s.m[1] = cp*st;  s.m[2] = sp*st;
    s.m[3] = -st;       s.m[4] = cp*ct;  s.m[5] = sp*ct;
    s.m[6] = 0.0f;      s.m[7] = -sp;    s.m[8] = cp;
    s.t[0] = bl*s.m[0]; s.t[1] = bl*s.m[1]; s.t[2] = bl*s.m[2];
}

__device__ __forceinline__ void reortho(Aff& s) {
    float inv = rsqrtf(fmaf(s.m[0], s.m[0], fmaf(s.m[1], s.m[1], s.m[2]*s.m[2])));
    s.m[0] *= inv; s.m[1] *= inv; s.m[2] *= inv;
    float d = fmaf(s.m[6], s.m[0], fmaf(s.m[7], s.m[1], s.m[8]*s.m[2]));
    s.m[6] = fmaf(-d, s.m[0], s.m[6]);
    s.m[7] = fmaf(-d, s.m[1], s.m[7]);
    s.m[8] = fmaf(-d, s.m[2], s.m[8]);
    inv = rsqrtf(fmaf(s.m[6], s.m[6], fmaf(s.m[7], s.m[7], s.m[8]*s.m[8])));
    s.m[6] *= inv; s.m[7] *= inv; s.m[8] *= inv;
    s.m[3] = s.m[7]*s.m[2] - s.m[8]*s.m[1];
    s.m[4] = s.m[8]*s.m[0] - s.m[6]*s.m[2];
    s.m[5] = s.m[6]*s.m[1] - s.m[7]*s.m[0];
}

__device__ __forceinline__ void aff_store(float* p, const Aff& a) {
#pragma unroll
    for (int i = 0; i < 9; i++) p[i] = a.m[i];
#pragma unroll
    for (int i = 0; i < 3; i++) p[9+i] = a.t[i];
}
__device__ __forceinline__ Aff aff_load(const float* p) {
    Aff a;
#pragma unroll
    for (int i = 0; i < 9; i++) a.m[i] = p[i];
#pragma unroll
    for (int i = 0; i < 3; i++) a.t[i] = p[9+i];
    return a;
}

__device__ __forceinline__ Aff aff_shfl_up(const Aff& a, int delta) {
    Aff r;
#pragma unroll
    for (int i = 0; i < 9; i++) r.m[i] = __shfl_up_sync(0xffffffffu, a.m[i], delta);
#pragma unroll
    for (int i = 0; i < 3; i++) r.t[i] = __shfl_up_sync(0xffffffffu, a.t[i], delta);
    return r;
}

// Stage a block tile into padded linear rows: st[(f/Q)*ROWF + f%Q].
__device__ __forceinline__ void stage_in(float* st, const float* __restrict__ gin,
                                          int nfl, int tid) {
    if (nfl == TILE_F) {
        const float4* g4 = (const float4*)gin;
        float4* s4 = (float4*)st;
        int j0 = tid / 12, k0 = tid - 12 * (tid / 12);
        int dst = j0 * ROW4 + k0;
#pragma unroll
        for (int it = 0; it < TILE_F/4/TPB; it++) {     // 12
            s4[dst] = g4[tid + it*TPB];
            dst += 16 * ROW4;
        }
    } else {
        int q0 = tid % Q, j0 = tid / Q;
        for (int f = tid; f < nfl; f += TPB) {
            st[j0*ROWF + q0] = gin[f];
            j0 += TPB/Q;
        }
    }
}

// ---------------------------------------------------------------------------
// K1: stage tile, DUAL half-chain walk (atoms 0-7 | 8-15, merged by cmb),
//     block scan, SoA stores.
// ---------------------------------------------------------------------------
__global__ void __launch_bounds__(TPB, 5) k1_chunks(const float* __restrict__ inner,
                                                    int n, int nchunks) {
    __shared__ float st[TPB * ROWF];    // 39936 B
    __shared__ float swc[NW * 12];
    int tid = threadIdx.x, b = blockIdx.x;
    int lane = tid & 31, wid = tid >> 5;
    int chunk = b * TPB + tid;

    long long tile0 = (long long)b * TILE_F;
    int nfl = (int)min((long long)TILE_F, (long long)n * 3 - tile0);
    stage_in(st, inner + tile0, nfl, tid);
    __syncthreads();

    Aff s = aff_identity();
    if (chunk < nchunks) {
        int base = chunk * C1;
        if (base + C1 <= n) {
            const float4* row4 = (const float4*)st + tid * ROW4;
            Aff s1, s2;
            float4 va = row4[0], vb = row4[1], vc = row4[2];
            float4 wa = row4[6], wb = row4[7], wc = row4[8];
            first_step(va.x, va.y, va.z, s1);
            first_step(wa.x, wa.y, wa.z, s2);
            chain_step(va.w, vb.x, vb.y, s1);
            chain_step(wa.w, wb.x, wb.y, s2);
            chain_step(vb.z, vb.w, vc.x, s1);
            chain_step(wb.z, wb.w, wc.x, s2);
            chain_step(vc.y, vc.z, vc.w, s1);
            chain_step(wc.y, wc.z, wc.w, s2);
            va = row4[3]; vb = row4[4]; vc = row4[5];
            wa = row4[9]; wb = row4[10]; wc = row4[11];
            chain_step(va.x, va.y, va.z, s1);
            chain_step(wa.x, wa.y, wa.z, s2);
            chain_step(va.w, vb.x, vb.y, s1);
            chain_step(wa.w, wb.x, wb.y, s2);
            chain_step(vb.z, vb.w, vc.x, s1);
            chain_step(wb.z, wb.w, wc.x, s2);
            chain_step(vc.y, vc.z, vc.w, s1);
            chain_step(wc.y, wc.z, wc.w, s2);
            s = cmb(s1, s2);               // half1 earlier, half2 later
        } else {
            int lim = n - base;
            const float* col = st + tid * ROWF;
            if (lim > 0) first_step(col[0], col[1], col[2], s);
            for (int k = 1; k < lim; k++)
                chain_step(col[3*k], col[3*k+1], col[3*k+2], s);
        }
    }
    // block scan (warp shuffle + cross-warp)
#pragma unroll
    for (int off = 1; off < 32; off <<= 1) {
        Aff p = aff_shfl_up(s, off);
        if (lane >= off) s = cmb(p, s);
    }
    if (lane == 31) aff_store(&swc[wid*12], s);
    __syncthreads();
    if (wid == 0) {
        Aff w = (lane < NW) ? aff_load(&swc[lane*12]) : aff_identity();
#pragma unroll
        for (int off = 1; off < NW; off <<= 1) {
            Aff p = aff_shfl_up(w, off);
            if (lane >= off) w = cmb(p, w);
        }
        if (lane < NW) aff_store(&swc[lane*12], w);
    }
    __syncthreads();
    if (wid > 0) s = cmb(aff_load(&swc[(wid-1)*12]), s);

    if (chunk < nchunks) {
#pragma unroll
        for (int c = 0; c < 9; c++)  g_cs[c*MAXCHUNKS + chunk] = s.m[c];
#pragma unroll
        for (int c = 0; c < 3; c++)  g_cs[(9+c)*MAXCHUNKS + chunk] = s.t[c];
    }
    if (tid == TPB - 1) aff_store(&g_blockComp[b*12], s);
}

// ---------------------------------------------------------------------------
// K2: scan block composites (hierarchical shuffle), seed with mainchain frame.
// ---------------------------------------------------------------------------
__global__ void __launch_bounds__(1024) k2_scan(int nb, const float* __restrict__ mc,
                                                float* __restrict__ out) {
    __shared__ float swc[32 * 12];
    __shared__ float s0sh[12];
    int tid = threadIdx.x, lane = tid & 31, wid = tid >> 5;
    if (tid == 0) {
        float Ax = mc[0], Ay = mc[1], Az = mc[2];
        float Bx = mc[3], By = mc[4], Bz = mc[5];
        float Cx = mc[6], Cy = mc[7], Cz = mc[8];
        float bx = Cx-Bx, by = Cy-By, bz = Cz-Bz;
        float inv = rsqrtf(bx*bx + by*by + bz*bz);
        bx *= inv; by *= inv; bz *= inv;
        float ux = Bx-Ax, uy = By-Ay, uz = Bz-Az;
        float nx = uy*bz - uz*by, ny = uz*bx - ux*bz, nz = ux*by - uy*bx;
        inv = rsqrtf(nx*nx + ny*ny + nz*nz);
        nx *= inv; ny *= inv; nz *= inv;
        s0sh[0]=bx; s0sh[1]=by; s0sh[2]=bz;
        s0sh[3]=ny*bz - nz*by; s0sh[4]=nz*bx - nx*bz; s0sh[5]=nx*by - ny*bx;
        s0sh[6]=nx; s0sh[7]=ny; s0sh[8]=nz;
        s0sh[9]=Cx; s0sh[10]=Cy; s0sh[11]=Cz;
    }
    if (tid < 9) out[tid] = mc[tid];
    Aff s = (tid < nb) ? aff_load(&g_blockComp[tid*12]) : aff_identity();
#pragma unroll
    for (int off = 1; off < 32; off <<= 1) {
        Aff p = aff_shfl_up(s, off);
        if (lane >= off) s = cmb(p, s);
    }
    if (lane == 31) aff_store(&swc[wid*12], s);
    __syncthreads();
    if (wid == 0) {
        Aff w = aff_load(&swc[lane*12]);   // 32 warps present in this kernel
#pragma unroll
        for (int off = 1; off < 32; off <<= 1) {
            Aff p = aff_shfl_up(w, off);
            if (lane >= off) w = cmb(p, w);
        }
        aff_store(&swc[lane*12], w);
    }
    __syncthreads();
    if (wid > 0) s = cmb(aff_load(&swc[(wid-1)*12]), s);  // full inclusive
    Aff e = aff_shfl_up(s, 1);                             // exclusive prefix
    if (lane == 0 && wid > 0) e = aff_load(&swc[(wid-1)*12]);
    if (tid < nb) {
        Aff s0 = aff_load(s0sh);
        Aff bp = (tid == 0) ? s0 : cmb(s0, e);
        reortho(bp);
        aff_store(&g_basePrefix[tid*12], bp);
    }
}

// ---------------------------------------------------------------------------
// K3: stage, seed from prefix; DUAL half-chain walk: half1 seeded (global
//     positions direct), half2 from identity (local), then 8 matvecs with
//     s_mid transform half2 in place. Division-free vectorized flush.
// ---------------------------------------------------------------------------
__global__ void __launch_bounds__(TPB, 5) k3_emit(const float* __restrict__ inner,
                                                  int n, int nchunks,
                                                  float* __restrict__ out) {
    __shared__ float st[TPB * ROWF];
    int tid = threadIdx.x, b = blockIdx.x;
    int chunk = b * TPB + tid;

    long long tile0 = (long long)b * TILE_F;
    int nfl = (int)min((long long)TILE_F, (long long)n * 3 - tile0);
    stage_in(st, inner + tile0, nfl, tid);
    __syncthreads();

    if (chunk < nchunks) {
        Aff s = aff_load(&g_basePrefix[b*12]);
        if (tid > 0) {
            Aff pre;
#pragma unroll
            for (int c = 0; c < 9; c++) pre.m[c] = g_cs[c*MAXCHUNKS + chunk - 1];
#pragma unroll
            for (int c = 0; c < 3; c++) pre.t[c] = g_cs[(9+c)*MAXCHUNKS + chunk - 1];
            s = cmb(s, pre);
        }
        reortho(s);
        int base = chunk * C1;
        if (base + C1 <= n) {
            float4* row4 = (float4*)st + tid * ROW4;
            Aff s2;
            // group 0: atoms 0-3 (seeded s) | atoms 8-11 (identity s2, local)
            {
                float4 va = row4[0], vb = row4[1], vc = row4[2];
                float4 wa = row4[6], wb = row4[7], wc = row4[8];
                float4 oa, ob, oc, pa, pb, pc;
                chain_step(va.x, va.y, va.z, s);  oa.x=s.t[0]; oa.y=s.t[1]; oa.z=s.t[2];
                first_step(wa.x, wa.y, wa.z, s2); pa.x=s2.t[0]; pa.y=s2.t[1]; pa.z=s2.t[2];
                chain_step(va.w, vb.x, vb.y, s);  oa.w=s.t[0]; ob.x=s.t[1]; ob.y=s.t[2];
                chain_step(wa.w, wb.x, wb.y, s2); pa.w=s2.t[0]; pb.x=s2.t[1]; pb.y=s2.t[2];
                chain_step(vb.z, vb.w, vc.x, s);  ob.z=s.t[0]; ob.w=s.t[1]; oc.x=s.t[2];
                chain_step(wb.z, wb.w, wc.x, s2); pb.z=s2.t[0]; pb.w=s2.t[1]; pc.x=s2.t[2];
                chain_step(vc.y, vc.z, vc.w, s);  oc.y=s.t[0]; oc.z=s.t[1]; oc.w=s.t[2];
                chain_step(wc.y, wc.z, wc.w, s2); pc.y=s2.t[0]; pc.z=s2.t[1]; pc.w=s2.t[2];
                row4[0] = oa; row4[1] = ob; row4[2] = oc;
                row4[6] = pa; row4[7] = pb; row4[8] = pc;
            }
            // group 1: atoms 4-7 | atoms 12-15
            {
                float4 va = row4[3], vb = row4[4],  vc = row4[5];
                float4 wa = row4[9], wb = row4[10], wc = row4[11];
                float4 oa, ob, oc, pa, pb, pc;
                chain_step(va.x, va.y, va.z, s);  oa.x=s.t[0]; oa.y=s.t[1]; oa.z=s.t[2];
                chain_step(wa.x, wa.y, wa.z, s2); pa.x=s2.t[0]; pa.y=s2.t[1]; pa.z=s2.t[2];
                chain_step(va.w, vb.x, vb.y, s);  oa.w=s.t[0]; ob.x=s.t[1]; ob.y=s.t[2];
                chain_step(wa.w, wb.x, wb.y, s2); pa.w=s2.t[0]; pb.x=s2.t[1]; pb.y=s2.t[2];
                chain_step(vb.z, vb.w, vc.x, s);  ob.z=s.t[0]; ob.w=s.t[1]; oc.x=s.t[2];
                chain_step(wb.z, wb.w, wc.x, s2); pb.z=s2.t[0]; pb.w=s2.t[1]; pc.x=s2.t[2];
                chain_step(vc.y, vc.z, vc.w, s);  oc.y=s.t[0]; oc.z=s.t[1]; oc.w=s.t[2];
                chain_step(wc.y, wc.z, wc.w, s2); pc.y=s2.t[0]; pc.z=s2.t[1]; pc.w=s2.t[2];
                row4[3] = oa; row4[4] = ob;  row4[5] = oc;
                row4[9] = pa; row4[10] = pb; row4[11] = pc;
            }
            // s is now s_mid (global state after atom 7). Transform half2
            // local positions in place: g = l.x*m[0..2] + l.y*m[3..5] + l.z*m[6..8] + t
#define XFORM(LX, LY, LZ, O0, O1, O2) \
            O0 = fmaf(LX, s.m[0], fmaf(LY, s.m[3], fmaf(LZ, s.m[6], s.t[0]))); \
            O1 = fmaf(LX, s.m[1], fmaf(LY, s.m[4], fmaf(LZ, s.m[7], s.t[1]))); \
            O2 = fmaf(LX, s.m[2], fmaf(LY, s.m[5], fmaf(LZ, s.m[8], s.t[2])));
#pragma unroll
            for (int r = 6; r < 12; r += 3) {
                float4 la = row4[r], lb = row4[r+1], lc = row4[r+2];
                float4 oa, ob, oc;
                XFORM(la.x, la.y, la.z, oa.x, oa.y, oa.z)
                XFORM(la.w, lb.x, lb.y, oa.w, ob.x, ob.y)
                XFORM(lb.z, lb.w, lc.x, ob.z, ob.w, oc.x)
                XFORM(lc.y, lc.z, lc.w, oc.y, oc.z, oc.w)
                row4[r] = oa; row4[r+1] = ob; row4[r+2] = oc;
            }
#undef XFORM
        } else {
            int lim = n - base;
            float* col = st + tid * ROWF;
            for (int k = 0; k < lim; k++) {
                chain_step(col[3*k], col[3*k+1], col[3*k+2], s);
                col[3*k]   = s.t[0];
                col[3*k+1] = s.t[1];
                col[3*k+2] = s.t[2];
            }
        }
    }
    __syncthreads();

    float* gout = out + 9 + tile0;
    if (nfl == TILE_F) {
        if (tid < 3) gout[tid] = st[tid];
        if (tid == 3) gout[TILE_F-1] = st[(TPB-1)*ROWF + Q - 1];
        float4* g4 = (float4*)(gout + 3);
        int f0 = 3 + 4*tid;
        int q0 = f0 % Q, j0 = f0 / Q;
        bool wrap = (q0 == Q - 1);
#pragma unroll
        for (int it = 0; it < 12; it++) {
            int m = tid + it*TPB;
            if (it == 11 && m >= (TILE_F-4)/4) break;   // m < 2303
            const float* r = st + j0*ROWF + q0;
            float4 v;
            if (!wrap) { v.x = r[0]; v.y = r[1]; v.z = r[2]; v.w = r[3]; }
            else {
                const float* r2 = st + (j0+1)*ROWF;
                v.x = r[0]; v.y = r2[0]; v.z = r2[1]; v.w = r2[2];
            }
            g4[m] = v;
            j0 += 16;
        }
    } else {
        int q0 = tid % Q, j0 = tid / Q;
        for (int f = tid; f < nfl; f += TPB) {
            gout[f] = st[j0*ROWF + q0];
            j0 += TPB/Q;
        }
    }
}

extern "C" void kernel_launch(void* const* d_in, const int* in_sizes, int n_in,
                              void* d_out, int out_size) {
    const float* inner = (const float*)d_in[0];
    const float* mc    = (const float*)d_in[2];
    float* out = (float*)d_out;
    int n = in_sizes[0] / 3;
    int nchunks = (n + C1 - 1) / C1;              // 187500
    int nblocks = (nchunks + TPB - 1) / TPB;      // 977  (<= 1024)

    k1_chunks<<<nblocks, TPB>>>(inner, n, nchunks);
    k2_scan<<<1, 1024>>>(nblocks, mc, out);
    k3_emit<<<nblocks, TPB>>>(inner, n, nchunks, out);
}

// round 16
// speedup vs baseline: 1.0847x; 1.0847x over previous
#include <cuda_runtime.h>
#include <cuda_bf16.h>
#include <cstdint>

// ============================================================================
// PNeRF coordinate extension as a chunked affine prefix scan (round 16).
// State (M, t): x_world = x_local @ M + t.  Step: M' = S M ; t' = t + bl*M'[0]
// Round 16 = best measured combination: R6 structure/tile/scan + Givens-
//   factored step (R12's k1, best measured) + R6's scalar k3 flush (the R12
//   vectorized flush regressed; reverted).
// ============================================================================

#define C1    16                 // atoms per chunk (per thread)
#define TPB   192                // chunks per block (6 warps)
#define NW    (TPB/32)
#define Q     (3*C1)             // 48 floats per chunk
#define ROWF  52                 // padded floats per row (208B, conflict-free .128)
#define ROW4  13                 // float4 per row
#define TILE_F (TPB*C1*3)        // 9216 floats per block tile
#define MAXCHUNKS 188160
#define MAXBLK    1024

struct Aff { float m[9]; float t[3]; };

__device__ float g_cs[12 * MAXCHUNKS];          // chunkScan, SoA: [comp][chunk]
__device__ float g_blockComp[MAXBLK * 12];
__device__ float g_basePrefix[MAXBLK * 12];

// ---------------------------------------------------------------------------
// Accurate fp32 sincos (immune to --use_fast_math): Cody-Waite + Cephes polys.
// ---------------------------------------------------------------------------
__device__ __forceinline__ void fsincos(float x, float& s, float& c) {
    float q = rintf(x * 0.6366197723675814f);
    float r = fmaf(q, -1.5707963705062866f, x);
    r = fmaf(q, 4.37113883e-8f, r);
    int iq = (int)q;
    float z = r * r;
    float ps = fmaf(z, -1.9515295891e-4f, 8.3321608736e-3f);
    ps = fmaf(z, ps, -1.6666654611e-1f);
    float sr = fmaf(r * z, ps, r);
    float pc = fmaf(z, 2.443315711809948e-5f, -1.388731625493765e-3f);
    pc = fmaf(z, pc, 4.166664568298827e-2f);
    float cr = fmaf(z * z, pc, fmaf(z, -0.5f, 1.0f));
    bool sw = (iq & 1);
    float ss = sw ? cr : sr;
    float cc = sw ? sr : cr;
    if (iq & 2)        ss = -ss;
    if ((iq + 1) & 2)  cc = -cc;
    s = ss; c = cc;
}

// Theta path: bond_angle in [1.9, 2.1] -> Cody-Waite quadrant is always 1.
__device__ __forceinline__ void fsincos_th(float x, float& s, float& c) {
    float r = (x - 1.5707963705062866f) + 4.37113883e-8f;
    float z = r * r;
    float ps = fmaf(z, -1.9515295891e-4f, 8.3321608736e-3f);
    ps = fmaf(z, ps, -1.6666654611e-1f);
    float sr = fmaf(r * z, ps, r);
    float pc = fmaf(z, 2.443315711809948e-5f, -1.388731625493765e-3f);
    pc = fmaf(z, pc, 4.166664568298827e-2f);
    float cr = fmaf(z * z, pc, fmaf(z, -0.5f, 1.0f));
    s = cr; c = -sr;
}

__device__ __forceinline__ Aff aff_identity() {
    Aff a = {{1,0,0, 0,1,0, 0,0,1}, {0,0,0}};
    return a;
}

// Combine: A earlier (or state), B later composite.
__device__ __forceinline__ Aff cmb(const Aff& A, const Aff& B) {
    Aff r;
#pragma unroll
    for (int i = 0; i < 3; i++) {
        float b0 = B.m[3*i], b1 = B.m[3*i+1], b2 = B.m[3*i+2];
#pragma unroll
        for (int j = 0; j < 3; j++)
            r.m[3*i+j] = fmaf(b0, A.m[j], fmaf(b1, A.m[3+j], b2 * A.m[6+j]));
    }
#pragma unroll
    for (int j = 0; j < 3; j++)
        r.t[j] = fmaf(B.t[0], A.m[j], fmaf(B.t[1], A.m[3+j],
                 fmaf(B.t[2], A.m[6+j], A.t[j])));
    return r;
}

// Givens-factored step: S = Rz(th) * Rx(ph), applied column-wise.
// Rx: u = cp*m1 + sp*m2 ; v = cp*m2 - sp*m1
// Rz: r0 = ct*m0 + st*u ; r1 = ct*u - st*m0 ; r2 = v
__device__ __forceinline__ void chain_step(float bl, float th, float ph, Aff& s) {
    float st, ct, sp, cp;
    fsincos_th(th, st, ct);
    fsincos(ph, sp, cp);
#pragma unroll
    for (int j = 0; j < 3; j++) {
        float m0 = s.m[j], m1 = s.m[3+j], m2 = s.m[6+j];
        float u  = fmaf(cp, m1, sp * m2);
        float v  = fmaf(cp, m2, -sp * m1);
        float r0 = fmaf(ct, m0, st * u);
        float r1 = fmaf(ct, u, -st * m0);
        s.m[j] = r0; s.m[3+j] = r1; s.m[6+j] = v;
        s.t[j] = fmaf(bl, r0, s.t[j]);
    }
}

// First step from identity: s = S, t = bl*S[0].
__device__ __forceinline__ void first_step(float bl, float th, float ph, Aff& s) {
    float st, ct, sp, cp;
    fsincos_th(th, st, ct);
    fsincos(ph, sp, cp);
    s.m[0] = ct;        s.m[1] = cp*st;  s.m[2] = sp*st;
    s.m[3] = -st;       s.m[4] = cp*ct;  s.m[5] = sp*ct;
    s.m[6] = 0.0f;      s.m[7] = -sp;    s.m[8] = cp;
    s.t[0] = bl*s.m[0]; s.t[1] = bl*s.m[1]; s.t[2] = bl*s.m[2];
}

__device__ __forceinline__ void reortho(Aff& s) {
    float inv = rsqrtf(fmaf(s.m[0], s.m[0], fmaf(s.m[1], s.m[1], s.m[2]*s.m[2])));
    s.m[0] *= inv; s.m[1] *= inv; s.m[2] *= inv;
    float d = fmaf(s.m[6], s.m[0], fmaf(s.m[7], s.m[1], s.m[8]*s.m[2]));
    s.m[6] = fmaf(-d, s.m[0], s.m[6]);
    s.m[7] = fmaf(-d, s.m[1], s.m[7]);
    s.m[8] = fmaf(-d, s.m[2], s.m[8]);
    inv = rsqrtf(fmaf(s.m[6], s.m[6], fmaf(s.m[7], s.m[7], s.m[8]*s.m[8])));
    s.m[6] *= inv; s.m[7] *= inv; s.m[8] *= inv;
    s.m[3] = s.m[7]*s.m[2] - s.m[8]*s.m[1];
    s.m[4] = s.m[8]*s.m[0] - s.m[6]*s.m[2];
    s.m[5] = s.m[6]*s.m[1] - s.m[7]*s.m[0];
}

__device__ __forceinline__ void aff_store(float* p, const Aff& a) {
#pragma unroll
    for (int i = 0; i < 9; i++) p[i] = a.m[i];
#pragma unroll
    for (int i = 0; i < 3; i++) p[9+i] = a.t[i];
}
__device__ __forceinline__ Aff aff_load(const float* p) {
    Aff a;
#pragma unroll
    for (int i = 0; i < 9; i++) a.m[i] = p[i];
#pragma unroll
    for (int i = 0; i < 3; i++) a.t[i] = p[9+i];
    return a;
}

__device__ __forceinline__ Aff aff_shfl_up(const Aff& a, int delta) {
    Aff r;
#pragma unroll
    for (int i = 0; i < 9; i++) r.m[i] = __shfl_up_sync(0xffffffffu, a.m[i], delta);
#pragma unroll
    for (int i = 0; i < 3; i++) r.t[i] = __shfl_up_sync(0xffffffffu, a.t[i], delta);
    return r;
}

// Stage a block tile into padded linear rows: st[(f/Q)*ROWF + f%Q].
__device__ __forceinline__ void stage_in(float* st, const float* __restrict__ gin,
                                          int nfl, int tid) {
    if (nfl == TILE_F) {
        const float4* g4 = (const float4*)gin;
        float4* s4 = (float4*)st;
        int j0 = tid / 12, k0 = tid - 12 * (tid / 12);
        int dst = j0 * ROW4 + k0;
#pragma unroll
        for (int it = 0; it < TILE_F/4/TPB; it++) {     // 12
            s4[dst] = g4[tid + it*TPB];
            dst += 16 * ROW4;
        }
    } else {
        int q0 = tid % Q, j0 = tid / Q;
        for (int f = tid; f < nfl; f += TPB) {
            st[j0*ROWF + q0] = gin[f];
            j0 += TPB/Q;
        }
    }
}

// ---------------------------------------------------------------------------
// K1: stage tile, per-chunk composites (vector walk), block scan, SoA stores.
// ---------------------------------------------------------------------------
__global__ void __launch_bounds__(TPB) k1_chunks(const float* __restrict__ inner,
                                                 int n, int nchunks) {
    __shared__ float st[TPB * ROWF];    // 39936 B
    __shared__ float swc[NW * 12];
    int tid = threadIdx.x, b = blockIdx.x;
    int lane = tid & 31, wid = tid >> 5;
    int chunk = b * TPB + tid;

    long long tile0 = (long long)b * TILE_F;
    int nfl = (int)min((long long)TILE_F, (long long)n * 3 - tile0);
    stage_in(st, inner + tile0, nfl, tid);
    __syncthreads();

    Aff s = aff_identity();
    if (chunk < nchunks) {
        int base = chunk * C1;
        if (base + C1 <= n) {
            const float4* row4 = (const float4*)st + tid * ROW4;
            float4 va = row4[0], vb = row4[1], vc = row4[2];
            first_step(va.x, va.y, va.z, s);
            chain_step(va.w, vb.x, vb.y, s);
            chain_step(vb.z, vb.w, vc.x, s);
            chain_step(vc.y, vc.z, vc.w, s);
#pragma unroll
            for (int G = 1; G < 4; G++) {
                va = row4[3*G]; vb = row4[3*G+1]; vc = row4[3*G+2];
                chain_step(va.x, va.y, va.z, s);
                chain_step(va.w, vb.x, vb.y, s);
                chain_step(vb.z, vb.w, vc.x, s);
                chain_step(vc.y, vc.z, vc.w, s);
            }
        } else {
            int lim = n - base;
            const float* col = st + tid * ROWF;
            if (lim > 0) first_step(col[0], col[1], col[2], s);
            for (int k = 1; k < lim; k++)
                chain_step(col[3*k], col[3*k+1], col[3*k+2], s);
        }
    }
    // block scan (warp shuffle + cross-warp)
#pragma unroll
    for (int off = 1; off < 32; off <<= 1) {
        Aff p = aff_shfl_up(s, off);
        if (lane >= off) s = cmb(p, s);
    }
    if (lane == 31) aff_store(&swc[wid*12], s);
    __syncthreads();
    if (wid == 0) {
        Aff w = (lane < NW) ? aff_load(&swc[lane*12]) : aff_identity();
#pragma unroll
        for (int off = 1; off < NW; off <<= 1) {
            Aff p = aff_shfl_up(w, off);
            if (lane >= off) w = cmb(p, w);
        }
        if (lane < NW) aff_store(&swc[lane*12], w);
    }
    __syncthreads();
    if (wid > 0) s = cmb(aff_load(&swc[(wid-1)*12]), s);

    if (chunk < nchunks) {
#pragma unroll
        for (int c = 0; c < 9; c++)  g_cs[c*MAXCHUNKS + chunk] = s.m[c];
#pragma unroll
        for (int c = 0; c < 3; c++)  g_cs[(9+c)*MAXCHUNKS + chunk] = s.t[c];
    }
    if (tid == TPB - 1) aff_store(&g_blockComp[b*12], s);
}

// ---------------------------------------------------------------------------
// K2: scan block composites (hierarchical shuffle), seed with mainchain frame.
// ---------------------------------------------------------------------------
__global__ void __launch_bounds__(1024) k2_scan(int nb, const float* __restrict__ mc,
                                                float* __restrict__ out) {
    __shared__ float swc[32 * 12];
    __shared__ float s0sh[12];
    int tid = threadIdx.x, lane = tid & 31, wid = tid >> 5;
    if (tid == 0) {
        float Ax = mc[0], Ay = mc[1], Az = mc[2];
        float Bx = mc[3], By = mc[4], Bz = mc[5];
        float Cx = mc[6], Cy = mc[7], Cz = mc[8];
        float bx = Cx-Bx, by = Cy-By, bz = Cz-Bz;
        float inv = rsqrtf(bx*bx + by*by + bz*bz);
        bx *= inv; by *= inv; bz *= inv;
        float ux = Bx-Ax, uy = By-Ay, uz = Bz-Az;
        float nx = uy*bz - uz*by, ny = uz*bx - ux*bz, nz = ux*by - uy*bx;
        inv = rsqrtf(nx*nx + ny*ny + nz*nz);
        nx *= inv; ny *= inv; nz *= inv;
        s0sh[0]=bx; s0sh[1]=by; s0sh[2]=bz;
        s0sh[3]=ny*bz - nz*by; s0sh[4]=nz*bx - nx*bz; s0sh[5]=nx*by - ny*bx;
        s0sh[6]=nx; s0sh[7]=ny; s0sh[8]=nz;
        s0sh[9]=Cx; s0sh[10]=Cy; s0sh[11]=Cz;
    }
    if (tid < 9) out[tid] = mc[tid];
    Aff s = (tid < nb) ? aff_load(&g_blockComp[tid*12]) : aff_identity();
#pragma unroll
    for (int off = 1; off < 32; off <<= 1) {
        Aff p = aff_shfl_up(s, off);
        if (lane >= off) s = cmb(p, s);
    }
    if (lane == 31) aff_store(&swc[wid*12], s);
    __syncthreads();
    if (wid == 0) {
        Aff w = aff_load(&swc[lane*12]);   // 32 warps present in this kernel
#pragma unroll
        for (int off = 1; off < 32; off <<= 1) {
            Aff p = aff_shfl_up(w, off);
            if (lane >= off) w = cmb(p, w);
        }
        aff_store(&swc[lane*12], w);
    }
    __syncthreads();
    if (wid > 0) s = cmb(aff_load(&swc[(wid-1)*12]), s);  // full inclusive
    Aff e = aff_shfl_up(s, 1);                             // exclusive prefix
    if (lane == 0 && wid > 0) e = aff_load(&swc[(wid-1)*12]);
    if (tid < nb) {
        Aff s0 = aff_load(s0sh);
        Aff bp = (tid == 0) ? s0 : cmb(s0, e);
        reortho(bp);
        aff_store(&g_basePrefix[tid*12], bp);
    }
}

// ---------------------------------------------------------------------------
// K3: stage, seed from prefix, vector walk with in-place float4 write-back,
//     R6's proven coalesced scalar flush (conflict-free, division-free).
// ---------------------------------------------------------------------------
__global__ void __launch_bounds__(TPB) k3_emit(const float* __restrict__ inner,
                                               int n, int nchunks,
                                               float* __restrict__ out) {
    __shared__ float st[TPB * ROWF];
    int tid = threadIdx.x, b = blockIdx.x;
    int chunk = b * TPB + tid;

    long long tile0 = (long long)b * TILE_F;
    int nfl = (int)min((long long)TILE_F, (long long)n * 3 - tile0);
    stage_in(st, inner + tile0, nfl, tid);
    __syncthreads();

    if (chunk < nchunks) {
        Aff s = aff_load(&g_basePrefix[b*12]);
        if (tid > 0) {
            Aff pre;
#pragma unroll
            for (int c = 0; c < 9; c++) pre.m[c] = g_cs[c*MAXCHUNKS + chunk - 1];
#pragma unroll
            for (int c = 0; c < 3; c++) pre.t[c] = g_cs[(9+c)*MAXCHUNKS + chunk - 1];
            s = cmb(s, pre);
        }
        reortho(s);
        int base = chunk * C1;
        if (base + C1 <= n) {
            float4* row4 = (float4*)st + tid * ROW4;
#pragma unroll
            for (int G = 0; G < 4; G++) {
                float4 va = row4[3*G], vb = row4[3*G+1], vc = row4[3*G+2];
                float4 oa, ob, oc;
                chain_step(va.x, va.y, va.z, s); oa.x=s.t[0]; oa.y=s.t[1]; oa.z=s.t[2];
                chain_step(va.w, vb.x, vb.y, s); oa.w=s.t[0]; ob.x=s.t[1]; ob.y=s.t[2];
                chain_step(vb.z, vb.w, vc.x, s); ob.z=s.t[0]; ob.w=s.t[1]; oc.x=s.t[2];
                chain_step(vc.y, vc.z, vc.w, s); oc.y=s.t[0]; oc.z=s.t[1]; oc.w=s.t[2];
                row4[3*G] = oa; row4[3*G+1] = ob; row4[3*G+2] = oc;
            }
        } else {
            int lim = n - base;
            float* col = st + tid * ROWF;
            for (int k = 0; k < lim; k++) {
                chain_step(col[3*k], col[3*k+1], col[3*k+2], s);
                col[3*k]   = s.t[0];
                col[3*k+1] = s.t[1];
                col[3*k+2] = s.t[2];
            }
        }
    }
    __syncthreads();
    // coalesced scalar flush; q invariant across iterations (TPB % Q == 0)
    float* gout = out + 9 + tile0;
    int q0 = tid % Q, j0 = tid / Q;
#pragma unroll 8
    for (int f = tid; f < nfl; f += TPB) {
        gout[f] = st[j0*ROWF + q0];
        j0 += TPB/Q;
    }
}

extern "C" void kernel_launch(void* const* d_in, const int* in_sizes, int n_in,
                              void* d_out, int out_size) {
    const float* inner = (const float*)d_in[0];
    const float* mc    = (const float*)d_in[2];
    float* out = (float*)d_out;
    int n = in_sizes[0] / 3;
    int nchunks = (n + C1 - 1) / C1;              // 187500
    int nblocks = (nchunks + TPB - 1) / TPB;      // 977  (<= 1024)

    k1_chunks<<<nblocks, TPB>>>(inner, n, nchunks);
    k2_scan<<<1, 1024>>>(nblocks, mc, out);
    k3_emit<<<nblocks, TPB>>>(inner, n, nchunks, out);
}

// round 17
// speedup vs baseline: 1.0944x; 1.0089x over previous
#include <cuda_runtime.h>
#include <cuda_bf16.h>
#include <cstdint>

// ============================================================================
// PNeRF coordinate extension as a chunked affine prefix scan (round 17).
// State (M, t): x_world = x_local @ M + t.  Step: M' = S M ; t' = t + bl*M'[0]
// Round 17 = R16 (best, 43.4us) + Programmatic Dependent Launch: k2/k3 launch
//   early; k3 stages its input tile concurrently with k1's tail + k2, then
//   cudaGridDependencySynchronize()s before consuming g_cs/g_basePrefix.
//   Math bit-identical to R16.
// ============================================================================

#define C1    16                 // atoms per chunk (per thread)
#define TPB   192                // chunks per block (6 warps)
#define NW    (TPB/32)
#define Q     (3*C1)             // 48 floats per chunk
#define ROWF  52                 // padded floats per row (208B, conflict-free .128)
#define ROW4  13                 // float4 per row
#define TILE_F (TPB*C1*3)        // 9216 floats per block tile
#define MAXCHUNKS 188160
#define MAXBLK    1024

struct Aff { float m[9]; float t[3]; };

__device__ float g_cs[12 * MAXCHUNKS];          // chunkScan, SoA: [comp][chunk]
__device__ float g_blockComp[MAXBLK * 12];
__device__ float g_basePrefix[MAXBLK * 12];

// ---------------------------------------------------------------------------
// Accurate fp32 sincos (immune to --use_fast_math): Cody-Waite + Cephes polys.
// ---------------------------------------------------------------------------
__device__ __forceinline__ void fsincos(float x, float& s, float& c) {
    float q = rintf(x * 0.6366197723675814f);
    float r = fmaf(q, -1.5707963705062866f, x);
    r = fmaf(q, 4.37113883e-8f, r);
    int iq = (int)q;
    float z = r * r;
    float ps = fmaf(z, -1.9515295891e-4f, 8.3321608736e-3f);
    ps = fmaf(z, ps, -1.6666654611e-1f);
    float sr = fmaf(r * z, ps, r);
    float pc = fmaf(z, 2.443315711809948e-5f, -1.388731625493765e-3f);
    pc = fmaf(z, pc, 4.166664568298827e-2f);
    float cr = fmaf(z * z, pc, fmaf(z, -0.5f, 1.0f));
    bool sw = (iq & 1);
    float ss = sw ? cr : sr;
    float cc = sw ? sr : cr;
    if (iq & 2)        ss = -ss;
    if ((iq + 1) & 2)  cc = -cc;
    s = ss; c = cc;
}

// Theta path: bond_angle in [1.9, 2.1] -> Cody-Waite quadrant is always 1.
__device__ __forceinline__ void fsincos_th(float x, float& s, float& c) {
    float r = (x - 1.5707963705062866f) + 4.37113883e-8f;
    float z = r * r;
    float ps = fmaf(z, -1.9515295891e-4f, 8.3321608736e-3f);
    ps = fmaf(z, ps, -1.6666654611e-1f);
    float sr = fmaf(r * z, ps, r);
    float pc = fmaf(z, 2.443315711809948e-5f, -1.388731625493765e-3f);
    pc = fmaf(z, pc, 4.166664568298827e-2f);
    float cr = fmaf(z * z, pc, fmaf(z, -0.5f, 1.0f));
    s = cr; c = -sr;
}

__device__ __forceinline__ Aff aff_identity() {
    Aff a = {{1,0,0, 0,1,0, 0,0,1}, {0,0,0}};
    return a;
}

// Combine: A earlier (or state), B later composite.
__device__ __forceinline__ Aff cmb(const Aff& A, const Aff& B) {
    Aff r;
#pragma unroll
    for (int i = 0; i < 3; i++) {
        float b0 = B.m[3*i], b1 = B.m[3*i+1], b2 = B.m[3*i+2];
#pragma unroll
        for (int j = 0; j < 3; j++)
            r.m[3*i+j] = fmaf(b0, A.m[j], fmaf(b1, A.m[3+j], b2 * A.m[6+j]));
    }
#pragma unroll
    for (int j = 0; j < 3; j++)
        r.t[j] = fmaf(B.t[0], A.m[j], fmaf(B.t[1], A.m[3+j],
                 fmaf(B.t[2], A.m[6+j], A.t[j])));
    return r;
}

// Givens-factored step: S = Rz(th) * Rx(ph), applied column-wise.
__device__ __forceinline__ void chain_step(float bl, float th, float ph, Aff& s) {
    float st, ct, sp, cp;
    fsincos_th(th, st, ct);
    fsincos(ph, sp, cp);
#pragma unroll
    for (int j = 0; j < 3; j++) {
        float m0 = s.m[j], m1 = s.m[3+j], m2 = s.m[6+j];
        float u  = fmaf(cp, m1, sp * m2);
        float v  = fmaf(cp, m2, -sp * m1);
        float r0 = fmaf(ct, m0, st * u);
        float r1 = fmaf(ct, u, -st * m0);
        s.m[j] = r0; s.m[3+j] = r1; s.m[6+j] = v;
        s.t[j] = fmaf(bl, r0, s.t[j]);
    }
}

// First step from identity: s = S, t = bl*S[0].
__device__ __forceinline__ void first_step(float bl, float th, float ph, Aff& s) {
    float st, ct, sp, cp;
    fsincos_th(th, st, ct);
    fsincos(ph, sp, cp);
    s.m[0] = ct;        s.m[1] = cp*st;  s.m[2] = sp*st;
    s.m[3] = -st;       s.m[4] = cp*ct;  s.m[5] = sp*ct;
    s.m[6] = 0.0f;      s.m[7] = -sp;    s.m[8] = cp;
    s.t[0] = bl*s.m[0]; s.t[1] = bl*s.m[1]; s.t[2] = bl*s.m[2];
}

__device__ __forceinline__ void reortho(Aff& s) {
    float inv = rsqrtf(fmaf(s.m[0], s.m[0], fmaf(s.m[1], s.m[1], s.m[2]*s.m[2])));
    s.m[0] *= inv; s.m[1] *= inv; s.m[2] *= inv;
    float d = fmaf(s.m[6], s.m[0], fmaf(s.m[7], s.m[1], s.m[8]*s.m[2]));
    s.m[6] = fmaf(-d, s.m[0], s.m[6]);
    s.m[7] = fmaf(-d, s.m[1], s.m[7]);
    s.m[8] = fmaf(-d, s.m[2], s.m[8]);
    inv = rsqrtf(fmaf(s.m[6], s.m[6], fmaf(s.m[7], s.m[7], s.m[8]*s.m[8])));
    s.m[6] *= inv; s.m[7] *= inv; s.m[8] *= inv;
    s.m[3] = s.m[7]*s.m[2] - s.m[8]*s.m[1];
    s.m[4] = s.m[8]*s.m[0] - s.m[6]*s.m[2];
    s.m[5] = s.m[6]*s.m[1] - s.m[7]*s.m[0];
}

__device__ __forceinline__ void aff_store(float* p, const Aff& a) {
#pragma unroll
    for (int i = 0; i < 9; i++) p[i] = a.m[i];
#pragma unroll
    for (int i = 0; i < 3; i++) p[9+i] = a.t[i];
}
__device__ __forceinline__ Aff aff_load(const float* p) {
    Aff a;
#pragma unroll
    for (int i = 0; i < 9; i++) a.m[i] = p[i];
#pragma unroll
    for (int i = 0; i < 3; i++) a.t[i] = p[9+i];
    return a;
}

__device__ __forceinline__ Aff aff_shfl_up(const Aff& a, int delta) {
    Aff r;
#pragma unroll
    for (int i = 0; i < 9; i++) r.m[i] = __shfl_up_sync(0xffffffffu, a.m[i], delta);
#pragma unroll
    for (int i = 0; i < 3; i++) r.t[i] = __shfl_up_sync(0xffffffffu, a.t[i], delta);
    return r;
}

// Stage a block tile into padded linear rows: st[(f/Q)*ROWF + f%Q].
__device__ __forceinline__ void stage_in(float* st, const float* __restrict__ gin,
                                          int nfl, int tid) {
    if (nfl == TILE_F) {
        const float4* g4 = (const float4*)gin;
        float4* s4 = (float4*)st;
        int j0 = tid / 12, k0 = tid - 12 * (tid / 12);
        int dst = j0 * ROW4 + k0;
#pragma unroll
        for (int it = 0; it < TILE_F/4/TPB; it++) {     // 12
            s4[dst] = g4[tid + it*TPB];
            dst += 16 * ROW4;
        }
    } else {
        int q0 = tid % Q, j0 = tid / Q;
        for (int f = tid; f < nfl; f += TPB) {
            st[j0*ROWF + q0] = gin[f];
            j0 += TPB/Q;
        }
    }
}

// ---------------------------------------------------------------------------
// K1: stage tile, per-chunk composites (vector walk), block scan, SoA stores.
// ---------------------------------------------------------------------------
__global__ void __launch_bounds__(TPB) k1_chunks(const float* __restrict__ inner,
                                                 int n, int nchunks) {
    __shared__ float st[TPB * ROWF];    // 39936 B
    __shared__ float swc[NW * 12];
    int tid = threadIdx.x, b = blockIdx.x;
    int lane = tid & 31, wid = tid >> 5;
    int chunk = b * TPB + tid;

    long long tile0 = (long long)b * TILE_F;
    int nfl = (int)min((long long)TILE_F, (long long)n * 3 - tile0);
    stage_in(st, inner + tile0, nfl, tid);
    __syncthreads();

    Aff s = aff_identity();
    if (chunk < nchunks) {
        int base = chunk * C1;
        if (base + C1 <= n) {
            const float4* row4 = (const float4*)st + tid * ROW4;
            float4 va = row4[0], vb = row4[1], vc = row4[2];
            first_step(va.x, va.y, va.z, s);
            chain_step(va.w, vb.x, vb.y, s);
            chain_step(vb.z, vb.w, vc.x, s);
            chain_step(vc.y, vc.z, vc.w, s);
#pragma unroll
            for (int G = 1; G < 4; G++) {
                va = row4[3*G]; vb = row4[3*G+1]; vc = row4[3*G+2];
                chain_step(va.x, va.y, va.z, s);
                chain_step(va.w, vb.x, vb.y, s);
                chain_step(vb.z, vb.w, vc.x, s);
                chain_step(vc.y, vc.z, vc.w, s);
            }
        } else {
            int lim = n - base;
            const float* col = st + tid * ROWF;
            if (lim > 0) first_step(col[0], col[1], col[2], s);
            for (int k = 1; k < lim; k++)
                chain_step(col[3*k], col[3*k+1], col[3*k+2], s);
        }
    }
    // block scan (warp shuffle + cross-warp)
#pragma unroll
    for (int off = 1; off < 32; off <<= 1) {
        Aff p = aff_shfl_up(s, off);
        if (lane >= off) s = cmb(p, s);
    }
    if (lane == 31) aff_store(&swc[wid*12], s);
    __syncthreads();
    if (wid == 0) {
        Aff w = (lane < NW) ? aff_load(&swc[lane*12]) : aff_identity();
#pragma unroll
        for (int off = 1; off < NW; off <<= 1) {
            Aff p = aff_shfl_up(w, off);
            if (lane >= off) w = cmb(p, w);
        }
        if (lane < NW) aff_store(&swc[lane*12], w);
    }
    __syncthreads();
    if (wid > 0) s = cmb(aff_load(&swc[(wid-1)*12]), s);

    if (chunk < nchunks) {
#pragma unroll
        for (int c = 0; c < 9; c++)  g_cs[c*MAXCHUNKS + chunk] = s.m[c];
#pragma unroll
        for (int c = 0; c < 3; c++)  g_cs[(9+c)*MAXCHUNKS + chunk] = s.t[c];
    }
    if (tid == TPB - 1) aff_store(&g_blockComp[b*12], s);
}

// ---------------------------------------------------------------------------
// K2: scan block composites (hierarchical shuffle), seed with mainchain frame.
// PDL: preamble (frame0 + out[0..8]) runs before grid-dependency sync.
// ---------------------------------------------------------------------------
__global__ void __launch_bounds__(1024) k2_scan(int nb, const float* __restrict__ mc,
                                                float* __restrict__ out) {
    __shared__ float swc[32 * 12];
    __shared__ float s0sh[12];
    int tid = threadIdx.x, lane = tid & 31, wid = tid >> 5;
    if (tid == 0) {
        float Ax = mc[0], Ay = mc[1], Az = mc[2];
        float Bx = mc[3], By = mc[4], Bz = mc[5];
        float Cx = mc[6], Cy = mc[7], Cz = mc[8];
        float bx = Cx-Bx, by = Cy-By, bz = Cz-Bz;
        float inv = rsqrtf(bx*bx + by*by + bz*bz);
        bx *= inv; by *= inv; bz *= inv;
        float ux = Bx-Ax, uy = By-Ay, uz = Bz-Az;
        float nx = uy*bz - uz*by, ny = uz*bx - ux*bz, nz = ux*by - uy*bx;
        inv = rsqrtf(nx*nx + ny*ny + nz*nz);
        nx *= inv; ny *= inv; nz *= inv;
        s0sh[0]=bx; s0sh[1]=by; s0sh[2]=bz;
        s0sh[3]=ny*bz - nz*by; s0sh[4]=nz*bx - nx*bz; s0sh[5]=nx*by - ny*bx;
        s0sh[6]=nx; s0sh[7]=ny; s0sh[8]=nz;
        s0sh[9]=Cx; s0sh[10]=Cy; s0sh[11]=Cz;
    }
    if (tid < 9) out[tid] = mc[tid];

    cudaGridDependencySynchronize();       // wait for k1's g_blockComp

    Aff s = (tid < nb) ? aff_load(&g_blockComp[tid*12]) : aff_identity();
#pragma unroll
    for (int off = 1; off < 32; off <<= 1) {
        Aff p = aff_shfl_up(s, off);
        if (lane >= off) s = cmb(p, s);
    }
    if (lane == 31) aff_store(&swc[wid*12], s);
    __syncthreads();
    if (wid == 0) {
        Aff w = aff_load(&swc[lane*12]);   // 32 warps present in this kernel
#pragma unroll
        for (int off = 1; off < 32; off <<= 1) {
            Aff p = aff_shfl_up(w, off);
            if (lane >= off) w = cmb(p, w);
        }
        aff_store(&swc[lane*12], w);
    }
    __syncthreads();
    if (wid > 0) s = cmb(aff_load(&swc[(wid-1)*12]), s);  // full inclusive
    Aff e = aff_shfl_up(s, 1);                             // exclusive prefix
    if (lane == 0 && wid > 0) e = aff_load(&swc[(wid-1)*12]);
    if (tid < nb) {
        Aff s0 = aff_load(s0sh);
        Aff bp = (tid == 0) ? s0 : cmb(s0, e);
        reortho(bp);
        aff_store(&g_basePrefix[tid*12], bp);
    }
}

// ---------------------------------------------------------------------------
// K3: stage (overlapped with k1/k2 via PDL), grid-sync, seed from prefix,
//     vector walk with in-place float4 write-back, scalar coalesced flush.
// ---------------------------------------------------------------------------
__global__ void __launch_bounds__(TPB) k3_emit(const float* __restrict__ inner,
                                               int n, int nchunks,
                                               float* __restrict__ out) {
    __shared__ float st[TPB * ROWF];
    int tid = threadIdx.x, b = blockIdx.x;
    int chunk = b * TPB + tid;

    long long tile0 = (long long)b * TILE_F;
    int nfl = (int)min((long long)TILE_F, (long long)n * 3 - tile0);
    stage_in(st, inner + tile0, nfl, tid);   // independent of k1/k2 output

    cudaGridDependencySynchronize();         // wait for g_cs / g_basePrefix
    __syncthreads();

    if (chunk < nchunks) {
        Aff s = aff_load(&g_basePrefix[b*12]);
        if (tid > 0) {
            Aff pre;
#pragma unroll
            for (int c = 0; c < 9; c++) pre.m[c] = g_cs[c*MAXCHUNKS + chunk - 1];
#pragma unroll
            for (int c = 0; c < 3; c++) pre.t[c] = g_cs[(9+c)*MAXCHUNKS + chunk - 1];
            s = cmb(s, pre);
        }
        reortho(s);
        int base = chunk * C1;
        if (base + C1 <= n) {
            float4* row4 = (float4*)st + tid * ROW4;
#pragma unroll
            for (int G = 0; G < 4; G++) {
                float4 va = row4[3*G], vb = row4[3*G+1], vc = row4[3*G+2];
                float4 oa, ob, oc;
                chain_step(va.x, va.y, va.z, s); oa.x=s.t[0]; oa.y=s.t[1]; oa.z=s.t[2];
                chain_step(va.w, vb.x, vb.y, s); oa.w=s.t[0]; ob.x=s.t[1]; ob.y=s.t[2];
                chain_step(vb.z, vb.w, vc.x, s); ob.z=s.t[0]; ob.w=s.t[1]; oc.x=s.t[2];
                chain_step(vc.y, vc.z, vc.w, s); oc.y=s.t[0]; oc.z=s.t[1]; oc.w=s.t[2];
                row4[3*G] = oa; row4[3*G+1] = ob; row4[3*G+2] = oc;
            }
        } else {
            int lim = n - base;
            float* col = st + tid * ROWF;
            for (int k = 0; k < lim; k++) {
                chain_step(col[3*k], col[3*k+1], col[3*k+2], s);
                col[3*k]   = s.t[0];
                col[3*k+1] = s.t[1];
                col[3*k+2] = s.t[2];
            }
        }
    }
    __syncthreads();
    // coalesced scalar flush; q invariant across iterations (TPB % Q == 0)
    float* gout = out + 9 + tile0;
    int q0 = tid % Q, j0 = tid / Q;
#pragma unroll 8
    for (int f = tid; f < nfl; f += TPB) {
        gout[f] = st[j0*ROWF + q0];
        j0 += TPB/Q;
    }
}

extern "C" void kernel_launch(void* const* d_in, const int* in_sizes, int n_in,
                              void* d_out, int out_size) {
    const float* inner = (const float*)d_in[0];
    const float* mc    = (const float*)d_in[2];
    float* out = (float*)d_out;
    int n = in_sizes[0] / 3;
    int nchunks = (n + C1 - 1) / C1;              // 187500
    int nblocks = (nchunks + TPB - 1) / TPB;      // 977  (<= 1024)

    // k1: plain launch
    k1_chunks<<<nblocks, TPB>>>(inner, n, nchunks);

    // k2, k3: programmatic dependent launch (overlap prologue with upstream)
    cudaLaunchAttribute attrs[1];
    attrs[0].id = cudaLaunchAttributeProgrammaticStreamSerialization;
    attrs[0].val.programmaticStreamSerializationAllowed = 1;

    {
        cudaLaunchConfig_t cfg = {};
        cfg.gridDim = dim3(1, 1, 1);
        cfg.blockDim = dim3(1024, 1, 1);
        cfg.dynamicSmemBytes = 0;
        cfg.stream = 0;
        cfg.attrs = attrs;
        cfg.numAttrs = 1;
        cudaLaunchKernelEx(&cfg, k2_scan, nblocks, mc, out);
    }
    {
        cudaLaunchConfig_t cfg = {};
        cfg.gridDim = dim3(nblocks, 1, 1);
        cfg.blockDim = dim3(TPB, 1, 1);
        cfg.dynamicSmemBytes = 0;
        cfg.stream = 0;
        cfg.attrs = attrs;
        cfg.numAttrs = 1;
        cudaLaunchKernelEx(&cfg, k3_emit, inner, n, nchunks, out);
    }
}